// round 14
// baseline (speedup 1.0000x reference)
#include <cuda_runtime.h>
#include <cuda_bf16.h>
#include <math.h>
#include <stdint.h>

// ---------------- static config ----------------
#define NWTOT 2048
#define NTASK 3072                   // 2048 windows + 1024 mlp tiles
#define TOK   262144
#define SHIFT 2
#define QSCL  0.2550540261150785f    // (hd^-0.5) * log2(e)
#define LOG2E 1.4426950408889634f
#define MASKV (-144.26950408889634f)
#define PITCH 272
#define NPERS 160

// ---------------- scratch ----------------
__device__ float g_x1[(size_t)TOK*128];
__device__ __nv_bfloat16 g_wq[384*128];
__device__ __nv_bfloat16 g_wp[128*128];
__device__ __nv_bfloat16 g_w1[512*128];
__device__ __nv_bfloat16 g_w2[128*512];
__device__ unsigned g_ct;            // unified work counter
__device__ unsigned g_band[128];     // per-(b,wh) completion counters

// ---------------- helpers ----------------
__device__ __forceinline__ uint32_t smem_u32(const void* p) {
    uint32_t a;
    asm("{ .reg .u64 t; cvta.to.shared.u64 t, %1; cvt.u32.u64 %0, t; }" : "=r"(a) : "l"(p));
    return a;
}
__device__ __forceinline__ void ldmx4(uint32_t* r, uint32_t addr) {
    asm volatile("ldmatrix.sync.aligned.m8n8.x4.shared.b16 {%0,%1,%2,%3}, [%4];"
        : "=r"(r[0]), "=r"(r[1]), "=r"(r[2]), "=r"(r[3]) : "r"(addr));
}
__device__ __forceinline__ void ldmx4t(uint32_t* r, uint32_t addr) {
    asm volatile("ldmatrix.sync.aligned.m8n8.x4.trans.shared.b16 {%0,%1,%2,%3}, [%4];"
        : "=r"(r[0]), "=r"(r[1]), "=r"(r[2]), "=r"(r[3]) : "r"(addr));
}
__device__ __forceinline__ void mma16816(float* c, const uint32_t* a, const uint32_t* b) {
    asm volatile("mma.sync.aligned.m16n8k16.row.col.f32.bf16.bf16.f32 "
        "{%0,%1,%2,%3}, {%4,%5,%6,%7}, {%8,%9}, {%0,%1,%2,%3};"
        : "+f"(c[0]), "+f"(c[1]), "+f"(c[2]), "+f"(c[3])
        : "r"(a[0]), "r"(a[1]), "r"(a[2]), "r"(a[3]), "r"(b[0]), "r"(b[1]));
}
#define CP16(sm, gp)  asm volatile("cp.async.cg.shared.global [%0], [%1], 16;" :: "r"(sm), "l"(gp))
#define CP_COMMIT()   asm volatile("cp.async.commit_group;" ::: "memory")
#define CP_WAIT(n)    asm volatile("cp.async.wait_group %0;" :: "n"(n) : "memory")

__device__ __forceinline__ uint32_t packbf(float a, float b) {
    __nv_bfloat162 h = __floats2bfloat162_rn(a, b);
    return *(uint32_t*)&h;
}
__device__ __forceinline__ float ex2(float v) {
    float r;
    asm("ex2.approx.f32 %0, %1;" : "=f"(r) : "f"(v));
    return r;
}
__device__ __forceinline__ float gelu_t(float v) {
    float u = v * (0.7978845608028654f + 0.0356774081f * v * v);
    float t;
    asm("tanh.approx.f32 %0, %1;" : "=f"(t) : "f"(u));
    return 0.5f * v * (1.f + t);
}

__device__ __forceinline__ void warp_mma32(uint32_t As, int apitch, uint32_t Bs, int bpitch,
                                           float acc[2][4][4], int wm, int wn, int lane) {
    const int ar = (lane & 7) + ((lane >> 3) & 1) * 8;
    const int ak = ((lane >> 4) & 1) * 16;
    const int br = (lane & 7) + ((lane >> 4) & 1) * 8;
    const int bk = ((lane >> 3) & 1) * 16;
    const uint32_t a_base = As + (wm * 32 + ar) * apitch + ak;
    const uint32_t b_base = Bs + (wn * 32 + br) * bpitch + bk;
    #pragma unroll
    for (int ks = 0; ks < 8; ks++) {
        uint32_t af[2][4], bf[2][4];
        #pragma unroll
        for (int mt = 0; mt < 2; mt++) ldmx4(af[mt], a_base + mt * 16 * apitch + ks * 32);
        #pragma unroll
        for (int np = 0; np < 2; np++) ldmx4(bf[np], b_base + np * 16 * bpitch + ks * 32);
        #pragma unroll
        for (int mt = 0; mt < 2; mt++) {
            mma16816(acc[mt][0], af[mt], &bf[0][0]);
            mma16816(acc[mt][1], af[mt], &bf[0][2]);
            mma16816(acc[mt][2], af[mt], &bf[1][0]);
            mma16816(acc[mt][3], af[mt], &bf[1][2]);
        }
    }
}
#define ZERO32(acc) do { \
    _Pragma("unroll") for (int _i = 0; _i < 2; _i++) \
    _Pragma("unroll") for (int _j = 0; _j < 4; _j++) \
    _Pragma("unroll") for (int _k = 0; _k < 4; _k++) acc[_i][_j][_k] = 0.f; } while (0)

// ============== kernel 0: weight pre-conversion + counter reset ==============
__global__ __launch_bounds__(256) void k_prep(const float* __restrict__ qkv_w,
                                              const float* __restrict__ proj_w,
                                              const float* __restrict__ fc1_w,
                                              const float* __restrict__ fc2_w) {
    int e = blockIdx.x * 256 + threadIdx.x;
    if (e == 0) g_ct = 0u;
    if (e < 128) g_band[e] = 0u;
    if (e < 49152) { int n = e >> 7, k = e & 127; g_wq[e] = __float2bfloat16(qkv_w[(size_t)k * 384 + n]); }
    if (e < 16384) { int n = e >> 7, k = e & 127; g_wp[e] = __float2bfloat16(proj_w[(size_t)k * 128 + n]); }
    if (e < 65536) {
        { int n = e >> 7, k = e & 127; g_w1[e] = __float2bfloat16(fc1_w[(size_t)k * 512 + n]); }
        { int n = e >> 9, k = e & 511; g_w2[e] = __float2bfloat16(fc2_w[(size_t)k * 128 + n]); }
    }
}

// smem offsets (bytes). Window task uses XS/QS/KS/VS/OS/WB; MLP task uses
// MX(=0)/MH/WA/WB2 (all < 208896). Bias lives at 208896+ and survives MLP tasks.
#define SM_XS 0
#define SM_QS 34816
#define SM_KS 69632
#define SM_VS 104448
#define SM_OS 139264
#define SM_WB 174080
#define MM_X  0
#define MM_H  69632
#define MM_WA 139264
#define MM_WB 174080
#define SM_BI 208896      // bias float[4][448] = 7168 B
#define SM_SL 216048      // task slot (4 B)
#define SM_ALL 216064

// ============== unified persistent kernel ==============
__global__ __launch_bounds__(512) void k_main(const float* __restrict__ x,
                                              const float* __restrict__ g1,
                                              const float* __restrict__ b1,
                                              const float* __restrict__ qkv_b,
                                              const float* __restrict__ rpb,
                                              const float* __restrict__ proj_b,
                                              const float* __restrict__ g2,
                                              const float* __restrict__ b2,
                                              const float* __restrict__ fc1_b,
                                              const float* __restrict__ fc2_b,
                                              float* __restrict__ out) {
    extern __shared__ char smc[];
    const uint32_t sb = smem_u32(smc);
    const int t = threadIdx.x, lane = t & 31, wid = t >> 5;
    float* bsm = (float*)(smc + SM_BI);
    volatile unsigned* slot = (volatile unsigned*)(smc + SM_SL);

    // rel-pos bias staged ONCE per CTA (pre-scaled by log2e)
    for (int i = t; i < 1764; i += 512) bsm[(i & 3) * 448 + (i >> 2)] = rpb[i] * LOG2E;

    const int wm = wid >> 2, wn = wid & 3;
    const int ar = (lane & 7) + ((lane >> 3) & 1) * 8;
    const int ak = ((lane >> 4) & 1) * 16;
    const int br = (lane & 7) + ((lane >> 4) & 1) * 8;
    const int bk = ((lane >> 3) & 1) * 16;

    while (true) {
        if (t == 0) *slot = atomicAdd(&g_ct, 1u);
        __syncthreads();                           // publish task; guard all smem reuse
        const unsigned task = *slot;
        if (task >= NTASK) break;

        if (task < NWTOT) {
            // ==================== WINDOW TASK ====================
            const unsigned win = task;
            const int b = win >> 8, wi = win & 255, wh = wi >> 4, ww = wi & 15;

            for (int i = t; i < 2048; i += 512) {
                int n = i >> 4, c16 = i & 15;
                CP16(sb + SM_WB + n * PITCH + c16 * 16, g_wq + (size_t)n * 128 + c16 * 8);
            }
            CP_COMMIT();
            for (int i = t; i < 2048; i += 512) {
                int n = i >> 4, c16 = i & 15;
                CP16(sb + SM_OS + n * PITCH + c16 * 16, g_wq + (size_t)(128 + n) * 128 + c16 * 8);
            }
            CP_COMMIT();

            // LN1
            {
                const int k4 = lane * 4;
                const float4 gv = *(const float4*)(g1 + k4);
                const float4 bv = *(const float4*)(b1 + k4);
                #pragma unroll
                for (int r8 = 0; r8 < 8; r8++) {
                    int m = wid * 8 + r8;
                    int r = (wh * 4 + (m >> 5) + SHIFT) & 63;
                    int c = (ww * 32 + (m & 31) + SHIFT) & 511;
                    float4 xv = *(const float4*)(x + ((size_t)(b * 64 + r) * 512 + c) * 128 + k4);
                    float s = xv.x + xv.y + xv.z + xv.w;
                    float ss = xv.x * xv.x + xv.y * xv.y + xv.z * xv.z + xv.w * xv.w;
                    #pragma unroll
                    for (int o = 16; o > 0; o >>= 1) {
                        s += __shfl_xor_sync(0xFFFFFFFFu, s, o);
                        ss += __shfl_xor_sync(0xFFFFFFFFu, ss, o);
                    }
                    float mean = s * (1.f / 128.f);
                    float rstd = rsqrtf(ss * (1.f / 128.f) - mean * mean + 1e-5f);
                    uint2 u;
                    u.x = packbf((xv.x - mean) * rstd * gv.x + bv.x, (xv.y - mean) * rstd * gv.y + bv.y);
                    u.y = packbf((xv.z - mean) * rstd * gv.z + bv.z, (xv.w - mean) * rstd * gv.w + bv.w);
                    *(uint2*)(smc + SM_XS + m * PITCH + k4 * 2) = u;
                }
            }
            CP_WAIT(0);
            __syncthreads();                       // X, w0, w1

            uint32_t xa[8][2][4];
            #pragma unroll
            for (int ks = 0; ks < 8; ks++)
                #pragma unroll
                for (int mt = 0; mt < 2; mt++)
                    ldmx4(xa[ks][mt], sb + SM_XS + (wm * 32 + mt * 16 + ar) * PITCH + ak + ks * 32);
            __syncthreads();                       // frags loaded; XS free

            for (int i = t; i < 2048; i += 512) {
                int n = i >> 4, c16 = i & 15;
                CP16(sb + SM_XS + n * PITCH + c16 * 16, g_wq + (size_t)(256 + n) * 128 + c16 * 8);
            }
            CP_COMMIT();

            const uint32_t wsrc[3] = { sb + SM_WB, sb + SM_OS, sb + SM_XS };
            for (int ct = 0; ct < 3; ct++) {
                if (ct == 2) {
                    CP_WAIT(0);
                    __syncthreads();               // w2 ready; WB free
                    for (int i = t; i < 2048; i += 512) {
                        int n = i >> 4, c16 = i & 15;
                        CP16(sb + SM_WB + n * PITCH + c16 * 16, g_wp + (size_t)n * 128 + c16 * 8);
                    }
                    CP_COMMIT();
                }
                float acc[2][4][4];
                ZERO32(acc);
                const uint32_t b_base = wsrc[ct] + (wn * 32 + br) * PITCH + bk;
                #pragma unroll
                for (int ks = 0; ks < 8; ks++) {
                    uint32_t bf[2][4];
                    ldmx4(bf[0], b_base + ks * 32);
                    ldmx4(bf[1], b_base + 16 * PITCH + ks * 32);
                    #pragma unroll
                    for (int mt = 0; mt < 2; mt++) {
                        mma16816(acc[mt][0], xa[ks][mt], &bf[0][0]);
                        mma16816(acc[mt][1], xa[ks][mt], &bf[0][2]);
                        mma16816(acc[mt][2], xa[ks][mt], &bf[1][0]);
                        mma16816(acc[mt][3], xa[ks][mt], &bf[1][2]);
                    }
                }
                const int dsto = (ct == 0) ? SM_QS : ((ct == 1) ? SM_KS : SM_VS);
                const float scl = (ct == 0) ? QSCL : 1.f;
                float bb[4][2];
                #pragma unroll
                for (int j = 0; j < 4; j++) {
                    int col = wn * 32 + j * 8 + (lane & 3) * 2;
                    bb[j][0] = qkv_b[ct * 128 + col];
                    bb[j][1] = qkv_b[ct * 128 + col + 1];
                }
                #pragma unroll
                for (int mt = 0; mt < 2; mt++) {
                    #pragma unroll
                    for (int half = 0; half < 2; half++) {
                        int row = wm * 32 + mt * 16 + (lane >> 2) + half * 8;
                        #pragma unroll
                        for (int j = 0; j < 4; j++) {
                            int col = wn * 32 + j * 8 + (lane & 3) * 2;
                            *(uint32_t*)(smc + dsto + row * PITCH + col * 2) =
                                packbf((acc[mt][j][half * 2 + 0] + bb[j][0]) * scl,
                                       (acc[mt][j][half * 2 + 1] + bb[j][1]) * scl);
                        }
                    }
                }
            }
            __syncthreads();                       // Q, K, V published

            // attention
            {
                const int h = wid & 3, g = wid >> 2;
                const bool edge = (wh == 15) || (ww == 15);

                uint32_t qa[2][2][4];
                #pragma unroll
                for (int mt = 0; mt < 2; mt++)
                    #pragma unroll
                    for (int kh = 0; kh < 2; kh++)
                        ldmx4(qa[mt][kh],
                              sb + SM_QS + (32 * g + 16 * mt + ar) * PITCH + 64 * h + ak + kh * 32);

                int rows[4], ib[4], rg[4];
                #pragma unroll
                for (int q = 0; q < 4; q++) {
                    int row = 32 * g + 16 * (q >> 1) + 8 * (q & 1) + (lane >> 2);
                    rows[q] = row;
                    ib[q] = (row >> 5) * 63 + (row & 31) + 220;
                    rg[q] = ((wh < 15) ? 0 : (((row >> 5) < 2) ? 1 : 2)) * 3
                          + ((ww < 15) ? 0 : (((row & 31) < 30) ? 1 : 2));
                }
                const float* bh = bsm + h * 448;

                float oacc[2][4][4];
                ZERO32(oacc);
                float rs[4] = {0.f, 0.f, 0.f, 0.f};

                #pragma unroll
                for (int np = 0; np < 8; np++) {
                    uint32_t kb0[4], kb1[4];
                    const uint32_t kbase = sb + SM_KS + (np * 16 + br) * PITCH + 64 * h + bk;
                    ldmx4(kb0, kbase);
                    ldmx4(kb1, kbase + 32);
                    float sacc[2][2][4];
                    ZERO32(sacc);
                    #pragma unroll
                    for (int mt = 0; mt < 2; mt++) {
                        mma16816(sacc[mt][0], qa[mt][0], &kb0[0]);
                        mma16816(sacc[mt][1], qa[mt][0], &kb0[2]);
                        mma16816(sacc[mt][0], qa[mt][1], &kb1[0]);
                        mma16816(sacc[mt][1], qa[mt][1], &kb1[2]);
                    }

                    uint32_t ap[2][4];
                    if (!edge) {
                        #pragma unroll
                        for (int mt = 0; mt < 2; mt++) {
                            #pragma unroll
                            for (int s2 = 0; s2 < 2; s2++) {
                                int col = np * 16 + s2 * 8 + (lane & 3) * 2;
                                int jo = (col >> 5) * 63 + (col & 31);
                                float p00 = ex2(sacc[mt][s2][0] + bh[ib[2*mt] - jo]);
                                float p01 = ex2(sacc[mt][s2][1] + bh[ib[2*mt] - jo - 1]);
                                float p10 = ex2(sacc[mt][s2][2] + bh[ib[2*mt+1] - jo]);
                                float p11 = ex2(sacc[mt][s2][3] + bh[ib[2*mt+1] - jo - 1]);
                                rs[2*mt]   += p00 + p01;
                                rs[2*mt+1] += p10 + p11;
                                ap[mt][s2 * 2 + 0] = packbf(p00, p01);
                                ap[mt][s2 * 2 + 1] = packbf(p10, p11);
                            }
                        }
                    } else {
                        #pragma unroll
                        for (int mt = 0; mt < 2; mt++) {
                            #pragma unroll
                            for (int s2 = 0; s2 < 2; s2++) {
                                int col = np * 16 + s2 * 8 + (lane & 3) * 2;
                                int jh = col >> 5, jw = col & 31;
                                int cg0 = ((wh < 15) ? 0 : ((jh < 2) ? 1 : 2)) * 3
                                        + ((ww < 15) ? 0 : ((jw < 30) ? 1 : 2));
                                int cg1 = ((wh < 15) ? 0 : ((jh < 2) ? 1 : 2)) * 3
                                        + ((ww < 15) ? 0 : ((jw + 1 < 30) ? 1 : 2));
                                int jo = jh * 63 + jw;
                                float p00 = ex2(sacc[mt][s2][0] + bh[ib[2*mt] - jo]
                                                + ((cg0 != rg[2*mt]) ? MASKV : 0.f));
                                float p01 = ex2(sacc[mt][s2][1] + bh[ib[2*mt] - jo - 1]
                                                + ((cg1 != rg[2*mt]) ? MASKV : 0.f));
                                float p10 = ex2(sacc[mt][s2][2] + bh[ib[2*mt+1] - jo]
                                                + ((cg0 != rg[2*mt+1]) ? MASKV : 0.f));
                                float p11 = ex2(sacc[mt][s2][3] + bh[ib[2*mt+1] - jo - 1]
                                                + ((cg1 != rg[2*mt+1]) ? MASKV : 0.f));
                                rs[2*mt]   += p00 + p01;
                                rs[2*mt+1] += p10 + p11;
                                ap[mt][s2 * 2 + 0] = packbf(p00, p01);
                                ap[mt][s2 * 2 + 1] = packbf(p10, p11);
                            }
                        }
                    }

                    uint32_t vb0[4], vb1[4];
                    const uint32_t va = sb + SM_VS + (16 * np + (lane & 15)) * PITCH + 64 * h
                                      + ((lane >> 4) & 1) * 16;
                    ldmx4t(vb0, va);
                    ldmx4t(vb1, va + 32);
                    #pragma unroll
                    for (int mt = 0; mt < 2; mt++) {
                        mma16816(oacc[mt][0], ap[mt], &vb0[0]);
                        mma16816(oacc[mt][1], ap[mt], &vb0[2]);
                        mma16816(oacc[mt][2], ap[mt], &vb1[0]);
                        mma16816(oacc[mt][3], ap[mt], &vb1[2]);
                    }
                }

                #pragma unroll
                for (int q = 0; q < 4; q++) {
                    rs[q] += __shfl_xor_sync(0xFFFFFFFFu, rs[q], 1);
                    rs[q] += __shfl_xor_sync(0xFFFFFFFFu, rs[q], 2);
                    rs[q] = 1.f / rs[q];
                }
                #pragma unroll
                for (int mt = 0; mt < 2; mt++) {
                    #pragma unroll
                    for (int j = 0; j < 4; j++) {
                        int col = 32 * h + j * 8 + (lane & 3) * 2;
                        *(uint32_t*)(smc + SM_OS + rows[2*mt] * PITCH + col * 2) =
                            packbf(oacc[mt][j][0] * rs[2*mt], oacc[mt][j][1] * rs[2*mt]);
                        *(uint32_t*)(smc + SM_OS + rows[2*mt+1] * PITCH + col * 2) =
                            packbf(oacc[mt][j][2] * rs[2*mt+1], oacc[mt][j][3] * rs[2*mt+1]);
                    }
                }
            }
            CP_WAIT(0);
            __syncthreads();                       // O + proj weights

            // proj + window reverse + residual -> g_x1
            float acc[2][4][4];
            ZERO32(acc);
            warp_mma32(sb + SM_OS, PITCH, sb + SM_WB, PITCH, acc, wm, wn, lane);
            #pragma unroll
            for (int mt = 0; mt < 2; mt++) {
                #pragma unroll
                for (int half = 0; half < 2; half++) {
                    int row = wm * 32 + mt * 16 + (lane >> 2) + half * 8;
                    int r = (wh * 4 + (row >> 5) + SHIFT) & 63;
                    int c = (ww * 32 + (row & 31) + SHIFT) & 511;
                    size_t base = ((size_t)(b * 64 + r) * 512 + c) * 128;
                    #pragma unroll
                    for (int j = 0; j < 4; j++) {
                        int n = wn * 32 + j * 8 + (lane & 3) * 2;
                        float2 xr = *(const float2*)(x + base + n);
                        float2 v;
                        v.x = xr.x + acc[mt][j][half * 2 + 0] + proj_b[n];
                        v.y = xr.y + acc[mt][j][half * 2 + 1] + proj_b[n + 1];
                        *(float2*)(g_x1 + base + n) = v;
                    }
                }
            }
            // release: make g_x1 writes visible, then count this window into its band
            __threadfence();
            __syncthreads();
            if (t == 0) atomicAdd(&g_band[b * 16 + wh], 1u);

        } else {
            // ==================== MLP TILE TASK ====================
            const unsigned m = task - NWTOT;
            const int band = m >> 3, sub = m & 7;
            const int bb_ = band >> 4, whb = band & 15;
            const int rr = (whb * 4 + SHIFT + (sub >> 1)) & 63;
            const size_t tok0 = ((size_t)(bb_ * 64 + rr) * 512) + (size_t)(sub & 1) * 256;
            const uint32_t Xs = sb + MM_X, Hs = sb + MM_H, WA = sb + MM_WA, WBu = sb + MM_WB;

            // prefetch fc1 chunk 0 (no data dependency)
            for (int i = t; i < 2048; i += 512) {
                int n = i >> 4, c16 = i & 15;
                CP16(WA + n * PITCH + c16 * 16, g_w1 + (size_t)n * 128 + c16 * 8);
            }
            CP_COMMIT();

            // acquire: wait for all 16 producer windows of this band
            if (t == 0) {
                unsigned v;
                do {
                    asm volatile("ld.acquire.gpu.u32 %0, [%1];"
                                 : "=r"(v) : "l"(&g_band[band]) : "memory");
                } while (v < 16u);
            }
            __syncthreads();

            // LN2 (g_x1 via .cg — L1 may be stale for cross-CTA writes in-launch)
            {
                const int k4 = lane * 4;
                const float4 gv = *(const float4*)(g2 + k4);
                const float4 bv = *(const float4*)(b2 + k4);
                #pragma unroll
                for (int r8 = 0; r8 < 16; r8++) {
                    int mrow = wid * 16 + r8;
                    float4 xv = __ldcg((const float4*)(g_x1 + (tok0 + mrow) * 128 + k4));
                    float s = xv.x + xv.y + xv.z + xv.w;
                    float ss = xv.x * xv.x + xv.y * xv.y + xv.z * xv.z + xv.w * xv.w;
                    #pragma unroll
                    for (int o = 16; o > 0; o >>= 1) {
                        s += __shfl_xor_sync(0xFFFFFFFFu, s, o);
                        ss += __shfl_xor_sync(0xFFFFFFFFu, ss, o);
                    }
                    float mean = s * (1.f / 128.f);
                    float rstd = rsqrtf(ss * (1.f / 128.f) - mean * mean + 1e-5f);
                    uint2 u;
                    u.x = packbf((xv.x - mean) * rstd * gv.x + bv.x, (xv.y - mean) * rstd * gv.y + bv.y);
                    u.y = packbf((xv.z - mean) * rstd * gv.z + bv.z, (xv.w - mean) * rstd * gv.w + bv.w);
                    *(uint2*)(smc + MM_X + mrow * PITCH + k4 * 2) = u;
                }
            }

            float acc2[4][4][4];
            #pragma unroll
            for (int i = 0; i < 4; i++)
                #pragma unroll
                for (int j = 0; j < 4; j++)
                    #pragma unroll
                    for (int k = 0; k < 4; k++) acc2[i][j][k] = 0.f;

            for (int ct = 0; ct < 4; ct++) {
                CP_WAIT(0);
                __syncthreads();
                for (int i = t; i < 2048; i += 512) {
                    int n = i >> 4, c16 = i & 15;
                    CP16(WBu + n * PITCH + c16 * 16, g_w2 + (size_t)n * 512 + ct * 128 + c16 * 8);
                }
                CP_COMMIT();

                #pragma unroll
                for (int s = 0; s < 2; s++) {
                    float a1[2][4][4];
                    ZERO32(a1);
                    const uint32_t a_base = Xs + (wm * 64 + s * 32 + ar) * PITCH + ak;
                    const uint32_t b_base = WA + (wn * 32 + br) * PITCH + bk;
                    #pragma unroll
                    for (int ks = 0; ks < 8; ks++) {
                        uint32_t af[2][4], bf[2][4];
                        #pragma unroll
                        for (int mt = 0; mt < 2; mt++) ldmx4(af[mt], a_base + mt * 16 * PITCH + ks * 32);
                        #pragma unroll
                        for (int np = 0; np < 2; np++) ldmx4(bf[np], b_base + np * 16 * PITCH + ks * 32);
                        #pragma unroll
                        for (int mt = 0; mt < 2; mt++) {
                            mma16816(a1[mt][0], af[mt], &bf[0][0]);
                            mma16816(a1[mt][1], af[mt], &bf[0][2]);
                            mma16816(a1[mt][2], af[mt], &bf[1][0]);
                            mma16816(a1[mt][3], af[mt], &bf[1][2]);
                        }
                    }
                    #pragma unroll
                    for (int mt = 0; mt < 2; mt++) {
                        #pragma unroll
                        for (int half = 0; half < 2; half++) {
                            int row = wm * 64 + s * 32 + mt * 16 + (lane >> 2) + half * 8;
                            #pragma unroll
                            for (int j = 0; j < 4; j++) {
                                int n = wn * 32 + j * 8 + (lane & 3) * 2;
                                float v0 = a1[mt][j][half * 2 + 0] + fc1_b[ct * 128 + n];
                                float v1 = a1[mt][j][half * 2 + 1] + fc1_b[ct * 128 + n + 1];
                                *(uint32_t*)(smc + MM_H + row * PITCH + n * 2) =
                                    packbf(gelu_t(v0), gelu_t(v1));
                            }
                        }
                    }
                }
                CP_WAIT(0);
                __syncthreads();
                if (ct < 3) {
                    for (int i = t; i < 2048; i += 512) {
                        int n = i >> 4, c16 = i & 15;
                        CP16(WA + n * PITCH + c16 * 16,
                             g_w1 + (size_t)((ct + 1) * 128 + n) * 128 + c16 * 8);
                    }
                    CP_COMMIT();
                }

                const uint32_t a2 = Hs + (wm * 64 + ar) * PITCH + ak;
                const uint32_t b2b = WBu + (wn * 32 + br) * PITCH + bk;
                #pragma unroll
                for (int ks = 0; ks < 8; ks++) {
                    uint32_t af[4][4], bf[2][4];
                    #pragma unroll
                    for (int mt = 0; mt < 4; mt++) ldmx4(af[mt], a2 + mt * 16 * PITCH + ks * 32);
                    #pragma unroll
                    for (int np = 0; np < 2; np++) ldmx4(bf[np], b2b + np * 16 * PITCH + ks * 32);
                    #pragma unroll
                    for (int mt = 0; mt < 4; mt++) {
                        mma16816(acc2[mt][0], af[mt], &bf[0][0]);
                        mma16816(acc2[mt][1], af[mt], &bf[0][2]);
                        mma16816(acc2[mt][2], af[mt], &bf[1][0]);
                        mma16816(acc2[mt][3], af[mt], &bf[1][2]);
                    }
                }
            }

            #pragma unroll
            for (int mt = 0; mt < 4; mt++) {
                #pragma unroll
                for (int half = 0; half < 2; half++) {
                    int row = wm * 64 + mt * 16 + (lane >> 2) + half * 8;
                    const float* xr = g_x1 + (tok0 + row) * 128;
                    float* orow = out + (tok0 + row) * 128;
                    #pragma unroll
                    for (int j = 0; j < 4; j++) {
                        int n = wn * 32 + j * 8 + (lane & 3) * 2;
                        float2 rv = __ldcg((const float2*)(xr + n));
                        float2 v;
                        v.x = rv.x + acc2[mt][j][half * 2 + 0] + fc2_b[n];
                        v.y = rv.y + acc2[mt][j][half * 2 + 1] + fc2_b[n + 1];
                        *(float2*)(orow + n) = v;
                    }
                }
            }
        }
    }
}

// ---------------- launcher ----------------
extern "C" void kernel_launch(void* const* d_in, const int* in_sizes, int n_in,
                              void* d_out, int out_size) {
    (void)in_sizes; (void)n_in; (void)out_size;
    const float* x      = (const float*)d_in[0];
    const float* g1     = (const float*)d_in[1];
    const float* b1     = (const float*)d_in[2];
    const float* qkv_w  = (const float*)d_in[3];
    const float* qkv_b  = (const float*)d_in[4];
    const float* rpb    = (const float*)d_in[5];
    const float* proj_w = (const float*)d_in[6];
    const float* proj_b = (const float*)d_in[7];
    const float* g2     = (const float*)d_in[8];
    const float* b2     = (const float*)d_in[9];
    const float* fc1_w  = (const float*)d_in[10];
    const float* fc1_b  = (const float*)d_in[11];
    const float* fc2_w  = (const float*)d_in[12];
    const float* fc2_b  = (const float*)d_in[13];
    float* out = (float*)d_out;

    cudaFuncSetAttribute(k_main, cudaFuncAttributeMaxDynamicSharedMemorySize, SM_ALL);

    k_prep<<<256, 256>>>(qkv_w, proj_w, fc1_w, fc2_w);
    k_main<<<NPERS, 512, SM_ALL>>>(x, g1, b1, qkv_b, rpb, proj_b,
                                   g2, b2, fc1_b, fc2_b, out);
}

// round 15
// speedup vs baseline: 1.0321x; 1.0321x over previous
#include <cuda_runtime.h>
#include <cuda_bf16.h>
#include <math.h>
#include <stdint.h>

// ---------------- static config ----------------
#define NWTOT 2048
#define NTILE 1024
#define TOK   262144
#define SHIFT 2
#define QSCL  0.2550540261150785f   // (hd^-0.5) * log2(e)
#define LOG2E 1.4426950408889634f
#define MASKV (-144.26950408889634f)
#define PITCH 272
#define NPERS 160

// ---------------- scratch ----------------
__device__ float g_x1[(size_t)TOK*128];
__device__ __nv_bfloat16 g_wq[384*128];
__device__ __nv_bfloat16 g_wp[128*128];
__device__ __nv_bfloat16 g_w1[512*128];
__device__ __nv_bfloat16 g_w2[128*512];
__device__ unsigned g_cw;
__device__ unsigned g_cm;

// ---------------- helpers ----------------
__device__ __forceinline__ uint32_t smem_u32(const void* p) {
    uint32_t a;
    asm("{ .reg .u64 t; cvta.to.shared.u64 t, %1; cvt.u32.u64 %0, t; }" : "=r"(a) : "l"(p));
    return a;
}
__device__ __forceinline__ void ldmx4(uint32_t* r, uint32_t addr) {
    asm volatile("ldmatrix.sync.aligned.m8n8.x4.shared.b16 {%0,%1,%2,%3}, [%4];"
        : "=r"(r[0]), "=r"(r[1]), "=r"(r[2]), "=r"(r[3]) : "r"(addr));
}
__device__ __forceinline__ void ldmx4t(uint32_t* r, uint32_t addr) {
    asm volatile("ldmatrix.sync.aligned.m8n8.x4.trans.shared.b16 {%0,%1,%2,%3}, [%4];"
        : "=r"(r[0]), "=r"(r[1]), "=r"(r[2]), "=r"(r[3]) : "r"(addr));
}
__device__ __forceinline__ void mma16816(float* c, const uint32_t* a, const uint32_t* b) {
    asm volatile("mma.sync.aligned.m16n8k16.row.col.f32.bf16.bf16.f32 "
        "{%0,%1,%2,%3}, {%4,%5,%6,%7}, {%8,%9}, {%0,%1,%2,%3};"
        : "+f"(c[0]), "+f"(c[1]), "+f"(c[2]), "+f"(c[3])
        : "r"(a[0]), "r"(a[1]), "r"(a[2]), "r"(a[3]), "r"(b[0]), "r"(b[1]));
}
#define CP16(sm, gp)  asm volatile("cp.async.cg.shared.global [%0], [%1], 16;" :: "r"(sm), "l"(gp))
#define CP_COMMIT()   asm volatile("cp.async.commit_group;" ::: "memory")
#define CP_WAIT(n)    asm volatile("cp.async.wait_group %0;" :: "n"(n) : "memory")

__device__ __forceinline__ uint32_t packbf(float a, float b) {
    __nv_bfloat162 h = __floats2bfloat162_rn(a, b);
    return *(uint32_t*)&h;
}
__device__ __forceinline__ float ex2(float v) {
    float r;
    asm("ex2.approx.f32 %0, %1;" : "=f"(r) : "f"(v));
    return r;
}
__device__ __forceinline__ float gelu_t(float v) {
    float u = v * (0.7978845608028654f + 0.0356774081f * v * v);
    float t;
    asm("tanh.approx.f32 %0, %1;" : "=f"(t) : "f"(u));
    return 0.5f * v * (1.f + t);
}

__device__ __forceinline__ void warp_mma32(uint32_t As, int apitch, uint32_t Bs, int bpitch,
                                           float acc[2][4][4], int wm, int wn, int lane) {
    const int ar = (lane & 7) + ((lane >> 3) & 1) * 8;
    const int ak = ((lane >> 4) & 1) * 16;
    const int br = (lane & 7) + ((lane >> 4) & 1) * 8;
    const int bk = ((lane >> 3) & 1) * 16;
    const uint32_t a_base = As + (wm * 32 + ar) * apitch + ak;
    const uint32_t b_base = Bs + (wn * 32 + br) * bpitch + bk;
    #pragma unroll
    for (int ks = 0; ks < 8; ks++) {
        uint32_t af[2][4], bf[2][4];
        #pragma unroll
        for (int mt = 0; mt < 2; mt++) ldmx4(af[mt], a_base + mt * 16 * apitch + ks * 32);
        #pragma unroll
        for (int np = 0; np < 2; np++) ldmx4(bf[np], b_base + np * 16 * bpitch + ks * 32);
        #pragma unroll
        for (int mt = 0; mt < 2; mt++) {
            mma16816(acc[mt][0], af[mt], &bf[0][0]);
            mma16816(acc[mt][1], af[mt], &bf[0][2]);
            mma16816(acc[mt][2], af[mt], &bf[1][0]);
            mma16816(acc[mt][3], af[mt], &bf[1][2]);
        }
    }
}
#define ZERO32(acc) do { \
    _Pragma("unroll") for (int _i = 0; _i < 2; _i++) \
    _Pragma("unroll") for (int _j = 0; _j < 4; _j++) \
    _Pragma("unroll") for (int _k = 0; _k < 4; _k++) acc[_i][_j][_k] = 0.f; } while (0)

// ============== kernel 0: weight pre-conversion + counter reset ==============
__global__ __launch_bounds__(256) void k_prep(const float* __restrict__ qkv_w,
                                              const float* __restrict__ proj_w,
                                              const float* __restrict__ fc1_w,
                                              const float* __restrict__ fc2_w) {
    int e = blockIdx.x * 256 + threadIdx.x;
    if (e == 0) { g_cw = 0u; g_cm = 0u; }
    if (e < 49152) { int n = e >> 7, k = e & 127; g_wq[e] = __float2bfloat16(qkv_w[(size_t)k * 384 + n]); }
    if (e < 16384) { int n = e >> 7, k = e & 127; g_wp[e] = __float2bfloat16(proj_w[(size_t)k * 128 + n]); }
    if (e < 65536) {
        { int n = e >> 7, k = e & 127; g_w1[e] = __float2bfloat16(fc1_w[(size_t)k * 512 + n]); }
        { int n = e >> 9, k = e & 511; g_w2[e] = __float2bfloat16(fc2_w[(size_t)k * 128 + n]); }
    }
}

// k_wmsa smem (bytes): W0|W1|WP persistent; KS; VS; B6 = X -> w2 -> O
#define SM_W0 0
#define SM_W1 34816
#define SM_WP 69632
#define SM_KS 104448
#define SM_VS 139264
#define SM_B6 174080
#define SM_BI 208896      // bias float[4][448]; slot at +7152
#define SM_WMSA 216064

// ============== kernel 1: persistent W-MSA (resident weights, Q in regs) ==============
__global__ __launch_bounds__(512) void k_wmsa(const float* __restrict__ x,
                                              const float* __restrict__ g1,
                                              const float* __restrict__ b1,
                                              const float* __restrict__ qkv_b,
                                              const float* __restrict__ rpb,
                                              const float* __restrict__ proj_b) {
    extern __shared__ char smc[];
    const uint32_t sb = smem_u32(smc);
    const int t = threadIdx.x, lane = t & 31, wid = t >> 5;
    float* bsm = (float*)(smc + SM_BI);
    volatile unsigned* wslot = (volatile unsigned*)(smc + SM_BI + 7152);

    // ---- one-time: stage persistent weights (w0, w1, proj_w) + bias ----
    for (int i = t; i < 2048; i += 512) {
        int n = i >> 4, c16 = i & 15;
        CP16(sb + SM_W0 + n * PITCH + c16 * 16, g_wq + (size_t)n * 128 + c16 * 8);
        CP16(sb + SM_W1 + n * PITCH + c16 * 16, g_wq + (size_t)(128 + n) * 128 + c16 * 8);
        CP16(sb + SM_WP + n * PITCH + c16 * 16, g_wp + (size_t)n * 128 + c16 * 8);
    }
    CP_COMMIT();
    for (int i = t; i < 1764; i += 512) bsm[(i & 3) * 448 + (i >> 2)] = rpb[i] * LOG2E;
    CP_WAIT(0);
    __syncthreads();

    const int wm = wid >> 2, wn = wid & 3;
    const int ar = (lane & 7) + ((lane >> 3) & 1) * 8;
    const int ak = ((lane >> 4) & 1) * 16;
    const int br = (lane & 7) + ((lane >> 4) & 1) * 8;
    const int bk = ((lane >> 3) & 1) * 16;

    // QKV bias fragments for this warp's column slice (loaded once)
    float bbq[4][2], bbk[4][2], bbv[4][2];
    #pragma unroll
    for (int j = 0; j < 4; j++) {
        int col = wn * 32 + j * 8 + (lane & 3) * 2;
        bbq[j][0] = qkv_b[col];           bbq[j][1] = qkv_b[col + 1];
        bbk[j][0] = qkv_b[128 + col];     bbk[j][1] = qkv_b[128 + col + 1];
        bbv[j][0] = qkv_b[256 + col];     bbv[j][1] = qkv_b[256 + col + 1];
    }

    while (true) {
        if (t == 0) *wslot = atomicAdd(&g_cw, 1u);
        __syncthreads();                           // publish win; prev-iter B6 reads done
        const unsigned win = *wslot;
        if (win >= NWTOT) break;
        const int b = win >> 8, wi = win & 255, wh = wi >> 4, ww = wi & 15;

        // --- LN1 -> X in B6 ---
        {
            const int k4 = lane * 4;
            const float4 gv = *(const float4*)(g1 + k4);
            const float4 bv = *(const float4*)(b1 + k4);
            #pragma unroll
            for (int r8 = 0; r8 < 8; r8++) {
                int m = wid * 8 + r8;
                int r = (wh * 4 + (m >> 5) + SHIFT) & 63;
                int c = (ww * 32 + (m & 31) + SHIFT) & 511;
                float4 xv = *(const float4*)(x + ((size_t)(b * 64 + r) * 512 + c) * 128 + k4);
                float s = xv.x + xv.y + xv.z + xv.w;
                float ss = xv.x * xv.x + xv.y * xv.y + xv.z * xv.z + xv.w * xv.w;
                #pragma unroll
                for (int o = 16; o > 0; o >>= 1) {
                    s += __shfl_xor_sync(0xFFFFFFFFu, s, o);
                    ss += __shfl_xor_sync(0xFFFFFFFFu, ss, o);
                }
                float mean = s * (1.f / 128.f);
                float rstd = rsqrtf(ss * (1.f / 128.f) - mean * mean + 1e-5f);
                uint2 u;
                u.x = packbf((xv.x - mean) * rstd * gv.x + bv.x, (xv.y - mean) * rstd * gv.y + bv.y);
                u.y = packbf((xv.z - mean) * rstd * gv.z + bv.z, (xv.w - mean) * rstd * gv.w + bv.w);
                *(uint2*)(smc + SM_B6 + m * PITCH + k4 * 2) = u;
            }
        }
        __syncthreads();                           // [1] X published

        // preload X A-fragments
        uint32_t xa[8][2][4];
        #pragma unroll
        for (int ks = 0; ks < 8; ks++)
            #pragma unroll
            for (int mt = 0; mt < 2; mt++)
                ldmx4(xa[ks][mt], sb + SM_B6 + (wm * 32 + mt * 16 + ar) * PITCH + ak + ks * 32);
        __syncthreads();                           // [2] frags loaded; B6 free

        // prefetch w2 (V weights) into B6 — only per-window weight load
        for (int i = t; i < 2048; i += 512) {
            int n = i >> 4, c16 = i & 15;
            CP16(sb + SM_B6 + n * PITCH + c16 * 16, g_wq + (size_t)(256 + n) * 128 + c16 * 8);
        }
        CP_COMMIT();

        // --- K = X @ w1 (persistent) ---
        {
            float acc[2][4][4];
            ZERO32(acc);
            const uint32_t b_base = sb + SM_W1 + (wn * 32 + br) * PITCH + bk;
            #pragma unroll
            for (int ks = 0; ks < 8; ks++) {
                uint32_t bf[2][4];
                ldmx4(bf[0], b_base + ks * 32);
                ldmx4(bf[1], b_base + 16 * PITCH + ks * 32);
                #pragma unroll
                for (int mt = 0; mt < 2; mt++) {
                    mma16816(acc[mt][0], xa[ks][mt], &bf[0][0]);
                    mma16816(acc[mt][1], xa[ks][mt], &bf[0][2]);
                    mma16816(acc[mt][2], xa[ks][mt], &bf[1][0]);
                    mma16816(acc[mt][3], xa[ks][mt], &bf[1][2]);
                }
            }
            #pragma unroll
            for (int mt = 0; mt < 2; mt++)
                #pragma unroll
                for (int half = 0; half < 2; half++) {
                    int row = wm * 32 + mt * 16 + (lane >> 2) + half * 8;
                    #pragma unroll
                    for (int j = 0; j < 4; j++) {
                        int col = wn * 32 + j * 8 + (lane & 3) * 2;
                        *(uint32_t*)(smc + SM_KS + row * PITCH + col * 2) =
                            packbf(acc[mt][j][half * 2 + 0] + bbk[j][0],
                                   acc[mt][j][half * 2 + 1] + bbk[j][1]);
                    }
                }
        }
        CP_WAIT(0);
        __syncthreads();                           // [3] w2 in B6

        // --- V = X @ w2 (B6) ---
        {
            float acc[2][4][4];
            ZERO32(acc);
            const uint32_t b_base = sb + SM_B6 + (wn * 32 + br) * PITCH + bk;
            #pragma unroll
            for (int ks = 0; ks < 8; ks++) {
                uint32_t bf[2][4];
                ldmx4(bf[0], b_base + ks * 32);
                ldmx4(bf[1], b_base + 16 * PITCH + ks * 32);
                #pragma unroll
                for (int mt = 0; mt < 2; mt++) {
                    mma16816(acc[mt][0], xa[ks][mt], &bf[0][0]);
                    mma16816(acc[mt][1], xa[ks][mt], &bf[0][2]);
                    mma16816(acc[mt][2], xa[ks][mt], &bf[1][0]);
                    mma16816(acc[mt][3], xa[ks][mt], &bf[1][2]);
                }
            }
            #pragma unroll
            for (int mt = 0; mt < 2; mt++)
                #pragma unroll
                for (int half = 0; half < 2; half++) {
                    int row = wm * 32 + mt * 16 + (lane >> 2) + half * 8;
                    #pragma unroll
                    for (int j = 0; j < 4; j++) {
                        int col = wn * 32 + j * 8 + (lane & 3) * 2;
                        *(uint32_t*)(smc + SM_VS + row * PITCH + col * 2) =
                            packbf(acc[mt][j][half * 2 + 0] + bbv[j][0],
                                   acc[mt][j][half * 2 + 1] + bbv[j][1]);
                    }
                }
        }

        // --- Q = X @ w0 (persistent) -> A-fragments directly in registers ---
        uint32_t qa[2][2][4];
        {
            float acc[2][4][4];
            ZERO32(acc);
            const uint32_t b_base = sb + SM_W0 + (wn * 32 + br) * PITCH + bk;
            #pragma unroll
            for (int ks = 0; ks < 8; ks++) {
                uint32_t bf[2][4];
                ldmx4(bf[0], b_base + ks * 32);
                ldmx4(bf[1], b_base + 16 * PITCH + ks * 32);
                #pragma unroll
                for (int mt = 0; mt < 2; mt++) {
                    mma16816(acc[mt][0], xa[ks][mt], &bf[0][0]);
                    mma16816(acc[mt][1], xa[ks][mt], &bf[0][2]);
                    mma16816(acc[mt][2], xa[ks][mt], &bf[1][0]);
                    mma16816(acc[mt][3], xa[ks][mt], &bf[1][2]);
                }
            }
            // C-fragment -> A-fragment identity (bias + QSCL folded)
            #pragma unroll
            for (int mt = 0; mt < 2; mt++)
                #pragma unroll
                for (int kh = 0; kh < 2; kh++) {
                    int j0 = 2 * kh, j1 = 2 * kh + 1;
                    qa[mt][kh][0] = packbf((acc[mt][j0][0] + bbq[j0][0]) * QSCL,
                                           (acc[mt][j0][1] + bbq[j0][1]) * QSCL);
                    qa[mt][kh][1] = packbf((acc[mt][j0][2] + bbq[j0][0]) * QSCL,
                                           (acc[mt][j0][3] + bbq[j0][1]) * QSCL);
                    qa[mt][kh][2] = packbf((acc[mt][j1][0] + bbq[j1][0]) * QSCL,
                                           (acc[mt][j1][1] + bbq[j1][1]) * QSCL);
                    qa[mt][kh][3] = packbf((acc[mt][j1][2] + bbq[j1][0]) * QSCL,
                                           (acc[mt][j1][3] + bbq[j1][1]) * QSCL);
                }
        }
        __syncthreads();                           // [4] K, V published; B6 free

        // --- attention: warp = (rows 32*wm, head wn), streaming ex2-softmax ---
        {
            const int h = wn, g = wm;
            const bool edge = (wh == 15) || (ww == 15);

            int rows[4], ib[4], rg[4];
            #pragma unroll
            for (int q = 0; q < 4; q++) {
                int row = 32 * g + 16 * (q >> 1) + 8 * (q & 1) + (lane >> 2);
                rows[q] = row;
                ib[q] = (row >> 5) * 63 + (row & 31) + 220;
                rg[q] = ((wh < 15) ? 0 : (((row >> 5) < 2) ? 1 : 2)) * 3
                      + ((ww < 15) ? 0 : (((row & 31) < 30) ? 1 : 2));
            }
            const float* bh = bsm + h * 448;

            float oacc[2][4][4];
            ZERO32(oacc);
            float rs[4] = {0.f, 0.f, 0.f, 0.f};

            #pragma unroll
            for (int np = 0; np < 8; np++) {
                uint32_t kb0[4], kb1[4];
                const uint32_t kbase = sb + SM_KS + (np * 16 + br) * PITCH + 64 * h + bk;
                ldmx4(kb0, kbase);
                ldmx4(kb1, kbase + 32);
                float sacc[2][2][4];
                ZERO32(sacc);
                #pragma unroll
                for (int mt = 0; mt < 2; mt++) {
                    mma16816(sacc[mt][0], qa[mt][0], &kb0[0]);
                    mma16816(sacc[mt][1], qa[mt][0], &kb0[2]);
                    mma16816(sacc[mt][0], qa[mt][1], &kb1[0]);
                    mma16816(sacc[mt][1], qa[mt][1], &kb1[2]);
                }

                uint32_t ap[2][4];
                if (!edge) {
                    #pragma unroll
                    for (int mt = 0; mt < 2; mt++)
                        #pragma unroll
                        for (int s2 = 0; s2 < 2; s2++) {
                            int col = np * 16 + s2 * 8 + (lane & 3) * 2;
                            int jo = (col >> 5) * 63 + (col & 31);
                            float p00 = ex2(sacc[mt][s2][0] + bh[ib[2*mt] - jo]);
                            float p01 = ex2(sacc[mt][s2][1] + bh[ib[2*mt] - jo - 1]);
                            float p10 = ex2(sacc[mt][s2][2] + bh[ib[2*mt+1] - jo]);
                            float p11 = ex2(sacc[mt][s2][3] + bh[ib[2*mt+1] - jo - 1]);
                            rs[2*mt]   += p00 + p01;
                            rs[2*mt+1] += p10 + p11;
                            ap[mt][s2 * 2 + 0] = packbf(p00, p01);
                            ap[mt][s2 * 2 + 1] = packbf(p10, p11);
                        }
                } else {
                    #pragma unroll
                    for (int mt = 0; mt < 2; mt++)
                        #pragma unroll
                        for (int s2 = 0; s2 < 2; s2++) {
                            int col = np * 16 + s2 * 8 + (lane & 3) * 2;
                            int jh = col >> 5, jw = col & 31;
                            int cg0 = ((wh < 15) ? 0 : ((jh < 2) ? 1 : 2)) * 3
                                    + ((ww < 15) ? 0 : ((jw < 30) ? 1 : 2));
                            int cg1 = ((wh < 15) ? 0 : ((jh < 2) ? 1 : 2)) * 3
                                    + ((ww < 15) ? 0 : ((jw + 1 < 30) ? 1 : 2));
                            int jo = jh * 63 + jw;
                            float p00 = ex2(sacc[mt][s2][0] + bh[ib[2*mt] - jo]
                                            + ((cg0 != rg[2*mt]) ? MASKV : 0.f));
                            float p01 = ex2(sacc[mt][s2][1] + bh[ib[2*mt] - jo - 1]
                                            + ((cg1 != rg[2*mt]) ? MASKV : 0.f));
                            float p10 = ex2(sacc[mt][s2][2] + bh[ib[2*mt+1] - jo]
                                            + ((cg0 != rg[2*mt+1]) ? MASKV : 0.f));
                            float p11 = ex2(sacc[mt][s2][3] + bh[ib[2*mt+1] - jo - 1]
                                            + ((cg1 != rg[2*mt+1]) ? MASKV : 0.f));
                            rs[2*mt]   += p00 + p01;
                            rs[2*mt+1] += p10 + p11;
                            ap[mt][s2 * 2 + 0] = packbf(p00, p01);
                            ap[mt][s2 * 2 + 1] = packbf(p10, p11);
                        }
                }

                uint32_t vb0[4], vb1[4];
                const uint32_t va = sb + SM_VS + (16 * np + (lane & 15)) * PITCH + 64 * h
                                  + ((lane >> 4) & 1) * 16;
                ldmx4t(vb0, va);
                ldmx4t(vb1, va + 32);
                #pragma unroll
                for (int mt = 0; mt < 2; mt++) {
                    mma16816(oacc[mt][0], ap[mt], &vb0[0]);
                    mma16816(oacc[mt][1], ap[mt], &vb0[2]);
                    mma16816(oacc[mt][2], ap[mt], &vb1[0]);
                    mma16816(oacc[mt][3], ap[mt], &vb1[2]);
                }
            }

            #pragma unroll
            for (int q = 0; q < 4; q++) {
                rs[q] += __shfl_xor_sync(0xFFFFFFFFu, rs[q], 1);
                rs[q] += __shfl_xor_sync(0xFFFFFFFFu, rs[q], 2);
                rs[q] = 1.f / rs[q];
            }
            #pragma unroll
            for (int mt = 0; mt < 2; mt++)
                #pragma unroll
                for (int j = 0; j < 4; j++) {
                    int col = 32 * h + j * 8 + (lane & 3) * 2;
                    *(uint32_t*)(smc + SM_B6 + rows[2*mt] * PITCH + col * 2) =
                        packbf(oacc[mt][j][0] * rs[2*mt], oacc[mt][j][1] * rs[2*mt]);
                    *(uint32_t*)(smc + SM_B6 + rows[2*mt+1] * PITCH + col * 2) =
                        packbf(oacc[mt][j][2] * rs[2*mt+1], oacc[mt][j][3] * rs[2*mt+1]);
                }
        }
        __syncthreads();                           // [5] O published

        // --- proj (persistent WP) + window reverse + residual ---
        float acc[2][4][4];
        ZERO32(acc);
        warp_mma32(sb + SM_B6, PITCH, sb + SM_WP, PITCH, acc, wm, wn, lane);
        #pragma unroll
        for (int mt = 0; mt < 2; mt++)
            #pragma unroll
            for (int half = 0; half < 2; half++) {
                int row = wm * 32 + mt * 16 + (lane >> 2) + half * 8;
                int r = (wh * 4 + (row >> 5) + SHIFT) & 63;
                int c = (ww * 32 + (row & 31) + SHIFT) & 511;
                size_t base = ((size_t)(b * 64 + r) * 512 + c) * 128;
                #pragma unroll
                for (int j = 0; j < 4; j++) {
                    int n = wn * 32 + j * 8 + (lane & 3) * 2;
                    float2 xr = *(const float2*)(x + base + n);
                    float2 v;
                    v.x = xr.x + acc[mt][j][half * 2 + 0] + proj_b[n];
                    v.y = xr.y + acc[mt][j][half * 2 + 1] + proj_b[n + 1];
                    *(float2*)(g_x1 + base + n) = v;
                }
            }
    }
}

// k_mlp smem: X (256x272) | Hc (256x272) | WA | WB | slot  (identical to R13)
#define MM_X  0
#define MM_H  69632
#define MM_WA 139264
#define MM_WB 174080
#define MM_SL 208896
#define SM_MLP3 208928

// ============== kernel 2: persistent fused MLP, 256 tokens/CTA (R13) ==============
__global__ __launch_bounds__(512) void k_mlp(const float* __restrict__ g2,
                                             const float* __restrict__ b2,
                                             const float* __restrict__ fc1_b,
                                             const float* __restrict__ fc2_b,
                                             float* __restrict__ out) {
    extern __shared__ char smc[];
    const uint32_t sb = smem_u32(smc);
    const uint32_t Xs = sb + MM_X, Hs = sb + MM_H, WA = sb + MM_WA, WBu = sb + MM_WB;
    const int t = threadIdx.x, lane = t & 31, wid = t >> 5;
    const int wm = wid >> 2, wn = wid & 3;
    volatile unsigned* tslot = (volatile unsigned*)(smc + MM_SL);

    const int ar = (lane & 7) + ((lane >> 3) & 1) * 8;
    const int ak = ((lane >> 4) & 1) * 16;
    const int br = (lane & 7) + ((lane >> 4) & 1) * 8;
    const int bk = ((lane >> 3) & 1) * 16;

    while (true) {
        if (t == 0) *tslot = atomicAdd(&g_cm, 1u);
        __syncthreads();
        const unsigned tile = *tslot;
        if (tile >= NTILE) break;

        for (int i = t; i < 2048; i += 512) {
            int n = i >> 4, c16 = i & 15;
            CP16(WA + n * PITCH + c16 * 16, g_w1 + (size_t)n * 128 + c16 * 8);
        }
        CP_COMMIT();

        {
            const int k4 = lane * 4;
            const float4 gv = *(const float4*)(g2 + k4);
            const float4 bv = *(const float4*)(b2 + k4);
            #pragma unroll
            for (int r8 = 0; r8 < 16; r8++) {
                int m = wid * 16 + r8;
                float4 xv = *(const float4*)(g_x1 + ((size_t)tile * 256 + m) * 128 + k4);
                float s = xv.x + xv.y + xv.z + xv.w;
                float ss = xv.x * xv.x + xv.y * xv.y + xv.z * xv.z + xv.w * xv.w;
                #pragma unroll
                for (int o = 16; o > 0; o >>= 1) {
                    s += __shfl_xor_sync(0xFFFFFFFFu, s, o);
                    ss += __shfl_xor_sync(0xFFFFFFFFu, ss, o);
                }
                float mean = s * (1.f / 128.f);
                float rstd = rsqrtf(ss * (1.f / 128.f) - mean * mean + 1e-5f);
                uint2 u;
                u.x = packbf((xv.x - mean) * rstd * gv.x + bv.x, (xv.y - mean) * rstd * gv.y + bv.y);
                u.y = packbf((xv.z - mean) * rstd * gv.z + bv.z, (xv.w - mean) * rstd * gv.w + bv.w);
                *(uint2*)(smc + MM_X + m * PITCH + k4 * 2) = u;
            }
        }

        float acc2[4][4][4];
        #pragma unroll
        for (int i = 0; i < 4; i++)
            #pragma unroll
            for (int j = 0; j < 4; j++)
                #pragma unroll
                for (int k = 0; k < 4; k++) acc2[i][j][k] = 0.f;

        for (int ct = 0; ct < 4; ct++) {
            CP_WAIT(0);
            __syncthreads();
            for (int i = t; i < 2048; i += 512) {
                int n = i >> 4, c16 = i & 15;
                CP16(WBu + n * PITCH + c16 * 16, g_w2 + (size_t)n * 512 + ct * 128 + c16 * 8);
            }
            CP_COMMIT();

            #pragma unroll
            for (int s = 0; s < 2; s++) {
                float a1[2][4][4];
                ZERO32(a1);
                const uint32_t a_base = Xs + (wm * 64 + s * 32 + ar) * PITCH + ak;
                const uint32_t b_base = WA + (wn * 32 + br) * PITCH + bk;
                #pragma unroll
                for (int ks = 0; ks < 8; ks++) {
                    uint32_t af[2][4], bf[2][4];
                    #pragma unroll
                    for (int mt = 0; mt < 2; mt++) ldmx4(af[mt], a_base + mt * 16 * PITCH + ks * 32);
                    #pragma unroll
                    for (int np = 0; np < 2; np++) ldmx4(bf[np], b_base + np * 16 * PITCH + ks * 32);
                    #pragma unroll
                    for (int mt = 0; mt < 2; mt++) {
                        mma16816(a1[mt][0], af[mt], &bf[0][0]);
                        mma16816(a1[mt][1], af[mt], &bf[0][2]);
                        mma16816(a1[mt][2], af[mt], &bf[1][0]);
                        mma16816(a1[mt][3], af[mt], &bf[1][2]);
                    }
                }
                #pragma unroll
                for (int mt = 0; mt < 2; mt++)
                    #pragma unroll
                    for (int half = 0; half < 2; half++) {
                        int row = wm * 64 + s * 32 + mt * 16 + (lane >> 2) + half * 8;
                        #pragma unroll
                        for (int j = 0; j < 4; j++) {
                            int n = wn * 32 + j * 8 + (lane & 3) * 2;
                            float v0 = a1[mt][j][half * 2 + 0] + fc1_b[ct * 128 + n];
                            float v1 = a1[mt][j][half * 2 + 1] + fc1_b[ct * 128 + n + 1];
                            *(uint32_t*)(smc + MM_H + row * PITCH + n * 2) =
                                packbf(gelu_t(v0), gelu_t(v1));
                        }
                    }
            }
            CP_WAIT(0);
            __syncthreads();
            if (ct < 3) {
                for (int i = t; i < 2048; i += 512) {
                    int n = i >> 4, c16 = i & 15;
                    CP16(WA + n * PITCH + c16 * 16,
                         g_w1 + (size_t)((ct + 1) * 128 + n) * 128 + c16 * 8);
                }
                CP_COMMIT();
            }

            const uint32_t a2 = Hs + (wm * 64 + ar) * PITCH + ak;
            const uint32_t b2b = WBu + (wn * 32 + br) * PITCH + bk;
            #pragma unroll
            for (int ks = 0; ks < 8; ks++) {
                uint32_t af[4][4], bf[2][4];
                #pragma unroll
                for (int mt = 0; mt < 4; mt++) ldmx4(af[mt], a2 + mt * 16 * PITCH + ks * 32);
                #pragma unroll
                for (int np = 0; np < 2; np++) ldmx4(bf[np], b2b + np * 16 * PITCH + ks * 32);
                #pragma unroll
                for (int mt = 0; mt < 4; mt++) {
                    mma16816(acc2[mt][0], af[mt], &bf[0][0]);
                    mma16816(acc2[mt][1], af[mt], &bf[0][2]);
                    mma16816(acc2[mt][2], af[mt], &bf[1][0]);
                    mma16816(acc2[mt][3], af[mt], &bf[1][2]);
                }
            }
        }

        #pragma unroll
        for (int mt = 0; mt < 4; mt++)
            #pragma unroll
            for (int half = 0; half < 2; half++) {
                int row = wm * 64 + mt * 16 + (lane >> 2) + half * 8;
                const float* xr = g_x1 + ((size_t)tile * 256 + row) * 128;
                float* orow = out + ((size_t)tile * 256 + row) * 128;
                #pragma unroll
                for (int j = 0; j < 4; j++) {
                    int n = wn * 32 + j * 8 + (lane & 3) * 2;
                    float2 rv = *(const float2*)(xr + n);
                    float2 v;
                    v.x = rv.x + acc2[mt][j][half * 2 + 0] + fc2_b[n];
                    v.y = rv.y + acc2[mt][j][half * 2 + 1] + fc2_b[n + 1];
                    *(float2*)(orow + n) = v;
                }
            }
    }
}

// ---------------- launcher ----------------
extern "C" void kernel_launch(void* const* d_in, const int* in_sizes, int n_in,
                              void* d_out, int out_size) {
    (void)in_sizes; (void)n_in; (void)out_size;
    const float* x      = (const float*)d_in[0];
    const float* g1     = (const float*)d_in[1];
    const float* b1     = (const float*)d_in[2];
    const float* qkv_w  = (const float*)d_in[3];
    const float* qkv_b  = (const float*)d_in[4];
    const float* rpb    = (const float*)d_in[5];
    const float* proj_w = (const float*)d_in[6];
    const float* proj_b = (const float*)d_in[7];
    const float* g2     = (const float*)d_in[8];
    const float* b2     = (const float*)d_in[9];
    const float* fc1_w  = (const float*)d_in[10];
    const float* fc1_b  = (const float*)d_in[11];
    const float* fc2_w  = (const float*)d_in[12];
    const float* fc2_b  = (const float*)d_in[13];
    float* out = (float*)d_out;

    cudaFuncSetAttribute(k_wmsa, cudaFuncAttributeMaxDynamicSharedMemorySize, SM_WMSA);
    cudaFuncSetAttribute(k_mlp,  cudaFuncAttributeMaxDynamicSharedMemorySize, SM_MLP3);

    k_prep<<<256, 256>>>(qkv_w, proj_w, fc1_w, fc2_w);
    k_wmsa<<<NPERS, 512, SM_WMSA>>>(x, g1, b1, qkv_b, rpb, proj_b);
    k_mlp<<<NPERS, 512, SM_MLP3>>>(g2, b2, fc1_b, fc2_b, out);
}